// round 11
// baseline (speedup 1.0000x reference)
#include <cuda_runtime.h>
#include <cstdint>

#define D_VOCAB 50257
#define D_MODEL 768
#define N_ROWS  4096          // BATCH * POS = 2 * 2048
#define SQRT_DM 27.712812921102035f   // sqrt(768)
#define NTHREADS 256
#define GRP 8                 // loads per thread per iteration (forced MLP)
#define NWORK (2 * N_ROWS)    // 8192 half-row work items
#define PBLOCKS 740           // 148 SMs x 5 resident blocks (regs~46) — persistent

// Scan [lo,hi) of p4 (uint4 view of one row past its prologue) for the single
// nonzero. Explicit group-of-8 loads with no intervening branches force
// front-batched LDG.128s; one OR-reduced branch per 512B. one_hot values are
// exactly 0.0f/1.0f, so integer checks are exact.
__device__ __forceinline__ void scan_range(
    const uint4* __restrict__ p4, int lo, int hi, int pre, int tid, int* s_col)
{
    int i = lo + tid;
    const int hi8 = hi - (GRP - 1) * NTHREADS;

    for (; i < hi8; i += GRP * NTHREADS) {
        uint4 v[GRP];
        #pragma unroll
        for (int k = 0; k < GRP; k++)
            v[k] = __ldcs(p4 + i + k * NTHREADS);

        unsigned any = 0;
        #pragma unroll
        for (int k = 0; k < GRP; k++)
            any |= v[k].x | v[k].y | v[k].z | v[k].w;

        if (any) {                                  // ~1 in 25K groups
            #pragma unroll
            for (int k = 0; k < GRP; k++) {
                int base = pre + ((i + k * NTHREADS) << 2);
                if (v[k].x) *s_col = base;
                if (v[k].y) *s_col = base + 1;
                if (v[k].z) *s_col = base + 2;
                if (v[k].w) *s_col = base + 3;
            }
        }
    }
    for (; i < hi; i += NTHREADS) {                 // remainder (< GRP iters)
        uint4 v = __ldcs(p4 + i);
        if (v.x | v.y | v.z | v.w) {
            int base = pre + (i << 2);
            if (v.x) *s_col = base;
            if (v.y) *s_col = base + 1;
            if (v.z) *s_col = base + 2;
            if (v.w) *s_col = base + 3;
        }
    }
}

// Persistent kernel: 740 resident blocks loop over 8192 half-row work items.
// Eliminates ~10 wave transitions of the non-persistent launch. The block
// whose half contains the nonzero performs the gather+scale+bias for the row.
__global__ void __launch_bounds__(NTHREADS) embed_persistent_kernel(
    const float* __restrict__ tokens,
    const float* __restrict__ W,
    const float* __restrict__ bias,
    float* __restrict__ out)
{
    const int tid = threadIdx.x;
    __shared__ int s_col;

    for (int work = blockIdx.x; work < NWORK; work += PBLOCKS) {
        const int row  = work >> 1;
        const int half = work & 1;
        const float* rp = tokens + (long)row * D_VOCAB;

        if (tid == 0) s_col = -1;
        __syncthreads();

        // Row start is (row*50257 mod 4) floats past a 16B boundary.
        const int mis = (int)(((uintptr_t)rp >> 2) & 3);
        const int pre = (4 - mis) & 3;             // scalar prologue count

        const uint4* __restrict__ p4 = reinterpret_cast<const uint4*>(rp + pre);
        const int n4   = (D_VOCAB - pre) >> 2;
        const int tail = (D_VOCAB - pre) & 3;
        const int n4h  = n4 >> 1;                  // half0: [0,n4h)  half1: [n4h,n4)

        if (half == 0) {
            if (tid < pre && __float_as_uint(rp[tid]) != 0u) s_col = tid;
            scan_range(p4, 0, n4h, pre, tid, &s_col);
        } else {
            scan_range(p4, n4h, n4, pre, tid, &s_col);
            const int tstart = pre + (n4 << 2);
            if (tid < tail && __float_as_uint(rp[tstart + tid]) != 0u)
                s_col = tstart + tid;
        }

        __syncthreads();
        const int col = s_col;

        // Only the half that found the nonzero emits the output row.
        if (col >= 0 && tid < D_MODEL / 4) {
            const float4 w = reinterpret_cast<const float4*>(W + (long)col * D_MODEL)[tid];
            const float4 b = reinterpret_cast<const float4*>(bias)[tid];
            float4 o;
            o.x = fmaf(w.x, SQRT_DM, b.x);
            o.y = fmaf(w.y, SQRT_DM, b.y);
            o.z = fmaf(w.z, SQRT_DM, b.z);
            o.w = fmaf(w.w, SQRT_DM, b.w);
            __stcs(reinterpret_cast<float4*>(out) + (long)row * (D_MODEL / 4) + tid, o);
        }
        __syncthreads();   // s_col reuse guard before next work item
    }
}

extern "C" void kernel_launch(void* const* d_in, const int* in_sizes, int n_in,
                              void* d_out, int out_size)
{
    const float* tokens = (const float*)d_in[0];   // [2, 2048, 50257] one-hot fp32
    const float* W      = (const float*)d_in[1];   // [50257, 768]
    const float* bias   = (const float*)d_in[2];   // [768]
    float* out          = (float*)d_out;           // [2, 2048, 768]

    embed_persistent_kernel<<<PBLOCKS, NTHREADS>>>(tokens, W, bias, out);
}

// round 12
// speedup vs baseline: 1.0183x; 1.0183x over previous
#include <cuda_runtime.h>
#include <cstdint>

#define D_VOCAB 50257
#define D_MODEL 768
#define N_ROWS  4096          // BATCH * POS = 2 * 2048
#define SQRT_DM 27.712812921102035f   // sqrt(768)
#define NTHREADS 256

// Two blocks per (batch,pos) row; each scans half of that row's 50257 one-hot
// floats. The block whose half contains the single nonzero performs the
// gather+scale+bias for the row. one_hot values are exactly 0.0f/1.0f, so
// integer-nonzero checks are exact.
//
// Converged configuration: all-int indices + unroll-8 keep ptxas front-batching
// 8 LDG.128s per thread (regs~39 signature); __ldcs streams the one-shot read
// past L2. Measured at the chip's path-independent LTS throughput cap
// (~6300 B/cyc ≈ 6.9 TB/s): DRAM ~87%, ncu ~122 us ≈ the 848 MB traffic floor.
__global__ void __launch_bounds__(NTHREADS) embed_fused_kernel(
    const float* __restrict__ tokens,
    const float* __restrict__ W,
    const float* __restrict__ bias,
    float* __restrict__ out)
{
    const int row  = blockIdx.x >> 1;
    const int half = blockIdx.x & 1;
    const int tid  = threadIdx.x;
    const float* rp = tokens + (long)row * D_VOCAB;

    __shared__ int s_col;
    if (tid == 0) s_col = -1;
    __syncthreads();

    // Row start is (row*50257 mod 4) floats past a 16B boundary.
    const int mis = (int)(((uintptr_t)rp >> 2) & 3);
    const int pre = (4 - mis) & 3;                 // scalar prologue count

    const uint4* __restrict__ p4 = reinterpret_cast<const uint4*>(rp + pre);
    const int n4   = (D_VOCAB - pre) >> 2;
    const int tail = (D_VOCAB - pre) & 3;
    const int n4h  = n4 >> 1;                      // half0: [0,n4h)  half1: [n4h,n4)

    if (half == 0) {
        if (tid < pre && __float_as_uint(rp[tid]) != 0u) s_col = tid;

        #pragma unroll 8
        for (int i = tid; i < n4h; i += NTHREADS) {
            uint4 v = __ldcs(p4 + i);              // streaming: evict-first
            if (v.x | v.y | v.z | v.w) {
                int base = pre + (i << 2);
                if (v.x) s_col = base;
                if (v.y) s_col = base + 1;
                if (v.z) s_col = base + 2;
                if (v.w) s_col = base + 3;
            }
        }
    } else {
        #pragma unroll 8
        for (int i = n4h + tid; i < n4; i += NTHREADS) {
            uint4 v = __ldcs(p4 + i);
            if (v.x | v.y | v.z | v.w) {
                int base = pre + (i << 2);
                if (v.x) s_col = base;
                if (v.y) s_col = base + 1;
                if (v.z) s_col = base + 2;
                if (v.w) s_col = base + 3;
            }
        }
        const int tstart = pre + (n4 << 2);
        if (tid < tail && __float_as_uint(rp[tstart + tid]) != 0u)
            s_col = tstart + tid;
    }

    __syncthreads();
    const int col = s_col;

    // Only the half that found the nonzero emits the output row.
    if (col >= 0 && tid < D_MODEL / 4) {
        const float4 w = reinterpret_cast<const float4*>(W + (long)col * D_MODEL)[tid];
        const float4 b = reinterpret_cast<const float4*>(bias)[tid];
        float4 o;
        o.x = fmaf(w.x, SQRT_DM, b.x);
        o.y = fmaf(w.y, SQRT_DM, b.y);
        o.z = fmaf(w.z, SQRT_DM, b.z);
        o.w = fmaf(w.w, SQRT_DM, b.w);
        reinterpret_cast<float4*>(out)[(long)row * (D_MODEL / 4) + tid] = o;
    }
}

extern "C" void kernel_launch(void* const* d_in, const int* in_sizes, int n_in,
                              void* d_out, int out_size)
{
    const float* tokens = (const float*)d_in[0];   // [2, 2048, 50257] one-hot fp32
    const float* W      = (const float*)d_in[1];   // [50257, 768]
    const float* bias   = (const float*)d_in[2];   // [768]
    float* out          = (float*)d_out;           // [2, 2048, 768]

    embed_fused_kernel<<<2 * N_ROWS, NTHREADS>>>(tokens, W, bias, out);
}